// round 11
// baseline (speedup 1.0000x reference)
#include <cuda_runtime.h>
#include <math.h>
#include <stdint.h>

#define BATCH 64
#define CIN   64
#define NNODE 4097
#define TNODE 4096
#define HID   128
#define LAT   64
#define EPSV  1e-5f

// -------- scratch (device globals; no allocation allowed) ----------
__device__ float    g_featsT[2][(size_t)BATCH * NNODE * CIN];   // (B,N,C), tf32-rounded
__device__ float    g_out1  [2][(size_t)BATCH * NNODE * HID];   // conv1 raw output (node0 row = 0)
__device__ float    g_h     [2][(size_t)BATCH * NNODE * HID];   // rna(relu(LN(out1)))
__device__ float    g_stats1[2][BATCH][2];                      // sum, sumsq of conv1 raw
__device__ float    g_stats2[2][BATCH][2];                      // sum, sumsq of conv2 raw
__device__ unsigned g_max2  [2][BATCH][HID];                    // per (b,o) max of conv2 raw (ordered)

// monotone float<->uint encoding so atomicMax(unsigned) == float max
__device__ __forceinline__ unsigned f2ord(float f) {
    unsigned u = __float_as_uint(f);
    return (u & 0x80000000u) ? ~u : (u | 0x80000000u);
}
__device__ __forceinline__ float ord2f(unsigned u) {
    return __uint_as_float((u & 0x80000000u) ? (u ^ 0x80000000u) : ~u);
}

// ---------------- small PTX helpers (all portable, sm_80+) ----------------
__device__ __forceinline__ float rna_tf32(float f) {
    uint32_t r;
    asm("cvt.rna.tf32.f32 %0, %1;" : "=r"(r) : "f"(f));
    return __uint_as_float(r);
}
__device__ __forceinline__ uint32_t smem_u32(const void* p) {
    uint32_t a;
    asm("{ .reg .u64 t; cvta.to.shared.u64 t, %1; cvt.u32.u64 %0, t; }" : "=r"(a) : "l"(p));
    return a;
}
__device__ __forceinline__ void cp_async16(uint32_t dst, const float* src) {
    asm volatile("cp.async.cg.shared.global [%0], [%1], 16;" :: "r"(dst), "l"(src));
}
__device__ __forceinline__ void cp_commit() {
    asm volatile("cp.async.commit_group;" ::: "memory");
}
template<int N> __device__ __forceinline__ void cp_wait() {
    asm volatile("cp.async.wait_group %0;" :: "n"(N) : "memory");
}
// D += A(16x8) * B(8x8), tf32 inputs (values already RNA-rounded), fp32 accum
__device__ __forceinline__ void mma_tf32(float* d, const float4& a, float b0, float b1) {
    asm volatile(
        "mma.sync.aligned.m16n8k8.row.col.f32.tf32.tf32.f32 "
        "{%0,%1,%2,%3}, {%4,%5,%6,%7}, {%8,%9}, {%0,%1,%2,%3};\n"
        : "+f"(d[0]), "+f"(d[1]), "+f"(d[2]), "+f"(d[3])
        : "r"(__float_as_uint(a.x)), "r"(__float_as_uint(a.y)),
          "r"(__float_as_uint(a.z)), "r"(__float_as_uint(a.w)),
          "r"(__float_as_uint(b0)), "r"(__float_as_uint(b1)));
}

// ---------------- init: zero stats, node-0 rows, max buffers ----------------
__global__ void init_kernel() {
    int i = blockIdx.x * blockDim.x + threadIdx.x;
    if (i < 2 * BATCH * HID) {
        int e = i / (BATCH * HID);
        int r = i % (BATCH * HID);
        int b = r / HID, o = r % HID;
        g_max2[e][b][o] = 0x80000000u;                       // encodes 0.0f (null node contributes 0)
        g_out1[e][(size_t)b * NNODE * HID + o] = 0.0f;       // zero null-node row
    }
    if (i < 2 * BATCH) {
        int e = i / BATCH, b = i % BATCH;
        g_stats1[e][b][0] = 0.f; g_stats1[e][b][1] = 0.f;
        g_stats2[e][b][0] = 0.f; g_stats2[e][b][1] = 0.f;
    }
}

// ---------------- transpose (B,C,N) -> (B,N,C), rounding to tf32 -------------
__global__ void transpose_kernel(const float* __restrict__ lf, const float* __restrict__ pf) {
    __shared__ float tile[32][33];
    int e = blockIdx.z >> 6;
    int b = blockIdx.z & 63;
    const float* src = e ? pf : lf;
    int n0 = blockIdx.x << 5, c0 = blockIdx.y << 5;
    int tx = threadIdx.x, ty = threadIdx.y;
#pragma unroll
    for (int i = 0; i < 32; i += 8) {
        int n = n0 + tx;
        if (n < NNODE) tile[ty + i][tx] = src[((size_t)b * CIN + c0 + ty + i) * NNODE + n];
    }
    __syncthreads();
#pragma unroll
    for (int i = 0; i < 32; i += 8) {
        int n = n0 + ty + i;
        if (n < NNODE)
            g_featsT[e][((size_t)b * NNODE + n) * CIN + c0 + tx] = rna_tf32(tile[tx][ty + i]);
    }
}

// ---------------- transform: g_h = rna(relu(LN1(g_out1))) ----------------
__global__ void transform_kernel() {
    const int P4 = NNODE * HID / 4;            // 131104 float4 per (e,b)
    int i = blockIdx.x * blockDim.x + threadIdx.x;
    if (i >= P4) return;
    int e = blockIdx.y >> 6, b = blockIdx.y & 63;
    float st = g_stats1[e][b][0], sst = g_stats1[e][b][1];
    const float cnt = (float)(HID * NNODE);
    float mean = st / cnt;
    float var = (sst - st * st / cnt) / (cnt - 1.f);
    float inv = 1.f / (sqrtf(var) + EPSV);
    float4 x = ((const float4*)(g_out1[e] + (size_t)b * NNODE * HID))[i];
    float4 y;
    y.x = rna_tf32(fmaxf(0.f, (x.x - mean) * inv));
    y.y = rna_tf32(fmaxf(0.f, (x.y - mean) * inv));
    y.z = rna_tf32(fmaxf(0.f, (x.z - mean) * inv));
    y.w = rna_tf32(fmaxf(0.f, (x.w - mean) * inv));
    ((float4*)(g_h[e] + (size_t)b * NNODE * HID))[i] = y;
}

// =================================================================================
// Warp-MMA tree conv: D[64(mh), 32nodes] = W * G^T via mma.sync m16n8k8 tf32.
// Grid (148, mh=2, e=2); CTA 256 thr = 8 warps (4m x 2n), warp tile M=16 x N=16.
// W fragment-packed in smem (LDS.128); G double-buffered, filled by cp.async
// (sources pre-rounded to tf32 bits: g_featsT / g_h).
// SECOND=false: store raw out1 + stats1.  SECOND=true: stats2 + per-(b,o) max.
// =================================================================================
template<int KD, bool SECOND>
__global__ void __launch_bounds__(256, SECOND ? 1 : 2) conv_mma_kernel(
    const int* __restrict__ children,
    const float* __restrict__ Wl, const float* __restrict__ bl,
    const float* __restrict__ Wp, const float* __restrict__ bp)
{
    constexpr int NT   = 32;              // nodes per tile
    constexpr int CPC  = KD / 3;          // floats per child slot (64 / 128)
    constexpr int KDP  = KD + 4;          // padded G row stride (floats)
    constexpr int NCH  = KD / 8;          // k-chunks
    constexpr int UNITS = CPC / 4;        // 16B units per child row (16 / 32)
    constexpr int TPB  = TNODE / NT;      // 128 tiles per example
    constexpr int TILES = BATCH * TPB;    // 8192 per (e, mh)
    constexpr int GCNT = NT * KDP;        // floats per G buffer

    const int e  = blockIdx.z;
    const int mh = blockIdx.y;
    const int per = (TILES + 147) / 148;
    const int t0 = blockIdx.x * per;
    const int t1 = min(TILES, t0 + per);
    if (t0 >= t1) return;

    extern __shared__ float smem[];
    float* s_W    = smem;                 // 64*KD floats, fragment-packed
    float* s_G    = smem + 64 * KD;       // 2 * GCNT
    float* s_bias = s_G + 2 * GCNT;       // 64
    const uint32_t g_u32 = smem_u32(s_G);

    const int tid = threadIdx.x;
    const int wid = tid >> 5, l = tid & 31;
    const int mp = wid >> 1, np = wid & 1;     // 4 m-warps x 2 n-warps

    // ---- fill W fragment-packed (pre-rounded tf32) + bias ----
    // layout: idx = (mp*NCH + q)*128 + lane*4 + reg
    //   m_loc = mp*16 + (lane>>2) + ((reg&1)<<3)
    //   k     = q*8 + (lane&3) + ((reg>>1)<<2)
    const float* Wg = e ? Wp : Wl;
    const float* bg = e ? bp : bl;
    for (int idx = tid; idx < 64 * KD; idx += 256) {
        int reg  = idx & 3;
        int lane = (idx >> 2) & 31;
        int rest = idx >> 7;
        int q    = rest % NCH;
        int mpp  = rest / NCH;
        int m_loc = mpp * 16 + (lane >> 2) + ((reg & 1) << 3);
        int k     = q * 8 + (lane & 3) + ((reg >> 1) << 2);
        int c = k % CPC, k3 = k / CPC;
        s_W[idx] = rna_tf32(Wg[(size_t)(mh * 64 + m_loc) * KD + c * 3 + k3]);
    }
    if (tid < 64) s_bias[tid] = bg[mh * 64 + tid];

    // ---- gather issue: raw cp.async of pre-transformed rows ----
    auto issue_gather = [&](int t, int buf) {
        int b = t >> 7;                       // / TPB
        int tl = t & 127;
        const int* chb = children + (size_t)b * 3 * TNODE + 3 * tl * NT;
        const float* sb = SECOND ? g_h[e] + (size_t)b * NNODE * HID
                                 : g_featsT[e] + (size_t)b * NNODE * CIN;
        uint32_t gd = g_u32 + (uint32_t)buf * (GCNT * 4);
#pragma unroll
        for (int idx = tid; idx < 3 * NT * UNITS; idx += 256) {
            int row = idx / UNITS;
            int u   = idx & (UNITS - 1);
            int i = row / 3, k3 = row - i * 3;
            int child = __ldg(chb + row);
            cp_async16(gd + (uint32_t)(i * KDP + k3 * CPC + u * 4) * 4,
                       sb + (size_t)child * CPC + u * 4);
        }
        cp_commit();
    };

    issue_gather(t0, 0);
    if (t0 + 1 < t1) issue_gather(t0 + 1, 1);

    for (int t = t0; t < t1; ++t) {
        int buf = (t - t0) & 1;
        if (t + 1 < t1) cp_wait<1>(); else cp_wait<0>();
        __syncthreads();

        // ---- MMA: warp tile M=16 x N=16, K=KD ----
        float d[2][4];
#pragma unroll
        for (int nt = 0; nt < 2; ++nt)
#pragma unroll
            for (int r = 0; r < 4; ++r) d[nt][r] = 0.f;

        const float* Gb = s_G + buf * GCNT;
        const int nrow0 = np * 16 + (l >> 2);
        const int kcol  = l & 3;
#pragma unroll 4
        for (int q = 0; q < NCH; ++q) {
            float4 a = ((const float4*)(s_W + ((mp * NCH + q) << 7)))[l];
            const float* gp0 = Gb + (size_t)(nrow0    ) * KDP + q * 8 + kcol;
            const float* gp1 = Gb + (size_t)(nrow0 + 8) * KDP + q * 8 + kcol;
            float b00 = gp0[0], b01 = gp0[4];
            float b10 = gp1[0], b11 = gp1[4];
            mma_tf32(d[0], a, b00, b01);
            mma_tf32(d[1], a, b10, b11);
        }

        // ---- epilogue ----
        int b = t >> 7, tl = t & 127;
        int n0 = 1 + tl * NT;
        float bb[2];
#pragma unroll
        for (int h = 0; h < 2; ++h)
            bb[h] = s_bias[mp * 16 + (l >> 2) + h * 8];

        float ls = 0.f, lss = 0.f;
        if (SECOND) {
            float mx[2] = {-3.4e38f, -3.4e38f};
#pragma unroll
            for (int nt = 0; nt < 2; ++nt)
#pragma unroll
                for (int r = 0; r < 4; ++r) {
                    float v = d[nt][r] + bb[r >> 1];
                    ls += v; lss += v * v;
                    mx[r >> 1] = fmaxf(mx[r >> 1], v);
                }
#pragma unroll
            for (int h = 0; h < 2; ++h) {
                float m = mx[h];
                m = fmaxf(m, __shfl_xor_sync(0xffffffffu, m, 1));
                m = fmaxf(m, __shfl_xor_sync(0xffffffffu, m, 2));
                if ((l & 3) == 0) {
                    int mg = mh * 64 + mp * 16 + (l >> 2) + h * 8;
                    atomicMax(&g_max2[e][b][mg], f2ord(m));
                }
            }
        } else {
            float* ob = g_out1[e] + ((size_t)b * NNODE + n0) * HID + mh * 64;
#pragma unroll
            for (int nt = 0; nt < 2; ++nt)
#pragma unroll
                for (int r = 0; r < 4; ++r) {
                    float v = d[nt][r] + bb[r >> 1];
                    int n_loc = np * 16 + nt * 8 + (l & 3) * 2 + (r & 1);
                    int m_loc = mp * 16 + (l >> 2) + (r >> 1) * 8;
                    ob[(size_t)n_loc * HID + m_loc] = v;
                    ls += v; lss += v * v;
                }
        }
#pragma unroll
        for (int off = 16; off; off >>= 1) {
            ls  += __shfl_xor_sync(0xffffffffu, ls, off);
            lss += __shfl_xor_sync(0xffffffffu, lss, off);
        }
        if (l == 0) {
            float* st = SECOND ? g_stats2[e][b] : g_stats1[e][b];
            atomicAdd(&st[0], ls);
            atomicAdd(&st[1], lss);
        }

        __syncthreads();                      // all warps done reading this buffer
        if (t + 2 < t1) issue_gather(t + 2, buf);
    }
}

// ---------------- finalize: LN2+relu on max, concat, mu/logvar GEMVs ---------------
__global__ void finalize_kernel(const float* __restrict__ Wmu, const float* __restrict__ bmu,
                                const float* __restrict__ Wlv, const float* __restrict__ blv,
                                float* __restrict__ out)
{
    __shared__ float comb[2 * HID];
    int b = blockIdx.x, tid = threadIdx.x;
    const float cntv = (float)(HID * NNODE);
#pragma unroll
    for (int e = 0; e < 2; ++e) {
        float st  = g_stats2[e][b][0];
        float sst = g_stats2[e][b][1];
        float mean = st / cntv;
        float var  = (sst - st * st / cntv) / (cntv - 1.f);
        float inv  = 1.f / (sqrtf(var) + EPSV);
        if (tid < HID) {
            float m = ord2f(g_max2[e][b][tid]);
            comb[e * HID + tid] = fmaxf(0.f, (m - mean) * inv);
        }
    }
    __syncthreads();
    if (tid < 64) {
        float acc = bmu[tid];
        for (int j = 0; j < 2 * HID; ++j) acc += Wmu[tid * 2 * HID + j] * comb[j];
        out[b * LAT + tid] = acc;
    } else if (tid < 128) {
        int t = tid - 64;
        float acc = blv[t];
        for (int j = 0; j < 2 * HID; ++j) acc += Wlv[t * 2 * HID + j] * comb[j];
        out[BATCH * LAT + b * LAT + t] = acc;
    }
}

// -------------------------------- launch --------------------------------
extern "C" void kernel_launch(void* const* d_in, const int* in_sizes, int n_in,
                              void* d_out, int out_size)
{
    const float* lf  = (const float*)d_in[0];
    const float* pf  = (const float*)d_in[1];
    const int*   ch  = (const int*)d_in[2];
    const float* Wl1 = (const float*)d_in[3];  const float* bl1 = (const float*)d_in[4];
    const float* Wl2 = (const float*)d_in[5];  const float* bl2 = (const float*)d_in[6];
    const float* Wp1 = (const float*)d_in[7];  const float* bp1 = (const float*)d_in[8];
    const float* Wp2 = (const float*)d_in[9];  const float* bp2 = (const float*)d_in[10];
    const float* Wmu = (const float*)d_in[11]; const float* bmu = (const float*)d_in[12];
    const float* Wlv = (const float*)d_in[13]; const float* blv = (const float*)d_in[14];
    float* out = (float*)d_out;

    // dynamic smem: W(64*KD) + 2 G buffers (NT*(KD+4)) + bias(64)
    const int SMEM1 = (64 * 192 + 2 * 32 * 196 + 64) * 4;   //  99,584 B (2 CTAs/SM)
    const int SMEM2 = (64 * 384 + 2 * 32 * 388 + 64) * 4;   // 197,888 B (1 CTA/SM)
    cudaFuncSetAttribute(conv_mma_kernel<192, false>,
                         cudaFuncAttributeMaxDynamicSharedMemorySize, SMEM1);
    cudaFuncSetAttribute(conv_mma_kernel<384, true>,
                         cudaFuncAttributeMaxDynamicSharedMemorySize, SMEM2);

    init_kernel<<<(2 * BATCH * HID + 255) / 256, 256>>>();
    transpose_kernel<<<dim3((NNODE + 31) / 32, CIN / 32, 2 * BATCH), dim3(32, 8)>>>(lf, pf);
    conv_mma_kernel<192, false><<<dim3(148, 2, 2), 256, SMEM1>>>(ch, Wl1, bl1, Wp1, bp1);
    transform_kernel<<<dim3((NNODE * HID / 4 + 255) / 256, 2 * BATCH), 256>>>();
    conv_mma_kernel<384, true ><<<dim3(148, 2, 2), 256, SMEM2>>>(ch, Wl2, bl2, Wp2, bp2);
    finalize_kernel<<<BATCH, 128>>>(Wmu, bmu, Wlv, blv, out);
}

// round 13
// speedup vs baseline: 1.6513x; 1.6513x over previous
#include <cuda_runtime.h>
#include <cuda_fp16.h>
#include <math.h>
#include <stdint.h>

#define BATCH 64
#define CIN   64
#define NNODE 4097
#define TNODE 4096
#define HID   128
#define LAT   64
#define EPSV  1e-5f

// -------- scratch (device globals; no allocation allowed) ----------
__device__ __half   g_featsT[2][(size_t)BATCH * NNODE * CIN];   // (B,N,C), fp16
__device__ float    g_out1  [2][(size_t)BATCH * NNODE * HID];   // conv1 raw output (node0 row = 0)
__device__ __half   g_h     [2][(size_t)BATCH * NNODE * HID];   // fp16(relu(LN(out1)))
__device__ float    g_stats1[2][BATCH][2];                      // sum, sumsq of conv1 raw
__device__ float    g_stats2[2][BATCH][2];                      // sum, sumsq of conv2 raw
__device__ unsigned g_max2  [2][BATCH][HID];                    // per (b,o) max of conv2 raw (ordered)

// monotone float<->uint encoding so atomicMax(unsigned) == float max
__device__ __forceinline__ unsigned f2ord(float f) {
    unsigned u = __float_as_uint(f);
    return (u & 0x80000000u) ? ~u : (u | 0x80000000u);
}
__device__ __forceinline__ float ord2f(unsigned u) {
    return __uint_as_float((u & 0x80000000u) ? (u ^ 0x80000000u) : ~u);
}

// ---------------- small PTX helpers (all portable, sm_80+) ----------------
__device__ __forceinline__ uint32_t smem_u32(const void* p) {
    uint32_t a;
    asm("{ .reg .u64 t; cvta.to.shared.u64 t, %1; cvt.u32.u64 %0, t; }" : "=r"(a) : "l"(p));
    return a;
}
__device__ __forceinline__ void cp_async16(uint32_t dst, const void* src) {
    asm volatile("cp.async.cg.shared.global [%0], [%1], 16;" :: "r"(dst), "l"(src));
}
__device__ __forceinline__ void cp_commit() {
    asm volatile("cp.async.commit_group;" ::: "memory");
}
template<int N> __device__ __forceinline__ void cp_wait() {
    asm volatile("cp.async.wait_group %0;" :: "n"(N) : "memory");
}
// D += A(16x16) * B(16x8), fp16 inputs, fp32 accumulate
__device__ __forceinline__ void mma_f16(float* d, const uint4& a, uint32_t b0, uint32_t b1) {
    asm volatile(
        "mma.sync.aligned.m16n8k16.row.col.f32.f16.f16.f32 "
        "{%0,%1,%2,%3}, {%4,%5,%6,%7}, {%8,%9}, {%0,%1,%2,%3};\n"
        : "+f"(d[0]), "+f"(d[1]), "+f"(d[2]), "+f"(d[3])
        : "r"(a.x), "r"(a.y), "r"(a.z), "r"(a.w), "r"(b0), "r"(b1));
}

// ---------------- init: zero stats, node-0 rows, max buffers ----------------
__global__ void init_kernel() {
    int i = blockIdx.x * blockDim.x + threadIdx.x;
    if (i < 2 * BATCH * HID) {
        int e = i / (BATCH * HID);
        int r = i % (BATCH * HID);
        int b = r / HID, o = r % HID;
        g_max2[e][b][o] = 0x80000000u;                       // encodes 0.0f (null node contributes 0)
        g_out1[e][(size_t)b * NNODE * HID + o] = 0.0f;       // zero null-node row (fp32)
        g_h[e][(size_t)b * NNODE * HID + o] = __float2half(0.f);  // zero null-node row (fp16)
    }
    if (i < 2 * BATCH) {
        int e = i / BATCH, b = i % BATCH;
        g_stats1[e][b][0] = 0.f; g_stats1[e][b][1] = 0.f;
        g_stats2[e][b][0] = 0.f; g_stats2[e][b][1] = 0.f;
    }
}

// ---------------- transpose (B,C,N) -> (B,N,C), rounding to fp16 -------------
__global__ void transpose_kernel(const float* __restrict__ lf, const float* __restrict__ pf) {
    __shared__ float tile[32][33];
    int e = blockIdx.z >> 6;
    int b = blockIdx.z & 63;
    const float* src = e ? pf : lf;
    int n0 = blockIdx.x << 5, c0 = blockIdx.y << 5;
    int tx = threadIdx.x, ty = threadIdx.y;
#pragma unroll
    for (int i = 0; i < 32; i += 8) {
        int n = n0 + tx;
        if (n < NNODE) tile[ty + i][tx] = src[((size_t)b * CIN + c0 + ty + i) * NNODE + n];
    }
    __syncthreads();
#pragma unroll
    for (int i = 0; i < 32; i += 8) {
        int n = n0 + ty + i;
        if (n < NNODE)
            g_featsT[e][((size_t)b * NNODE + n) * CIN + c0 + tx] = __float2half_rn(tile[tx][ty + i]);
    }
}

// ---------------- transform: g_h = fp16(relu(LN1(g_out1))) ----------------
__global__ void transform_kernel() {
    const int P4 = NNODE * HID / 4;            // 131104 float4 per (e,b)
    int i = blockIdx.x * blockDim.x + threadIdx.x;
    if (i >= P4) return;
    int e = blockIdx.y >> 6, b = blockIdx.y & 63;
    float st = g_stats1[e][b][0], sst = g_stats1[e][b][1];
    const float cnt = (float)(HID * NNODE);
    float mean = st / cnt;
    float var = (sst - st * st / cnt) / (cnt - 1.f);
    float inv = 1.f / (sqrtf(var) + EPSV);
    float4 x = ((const float4*)(g_out1[e] + (size_t)b * NNODE * HID))[i];
    __half2 lo = __floats2half2_rn(fmaxf(0.f, (x.x - mean) * inv),
                                   fmaxf(0.f, (x.y - mean) * inv));
    __half2 hi = __floats2half2_rn(fmaxf(0.f, (x.z - mean) * inv),
                                   fmaxf(0.f, (x.w - mean) * inv));
    uint2 pk;
    pk.x = *(uint32_t*)&lo;
    pk.y = *(uint32_t*)&hi;
    ((uint2*)(g_h[e] + (size_t)b * NNODE * HID))[i] = pk;
}

// =================================================================================
// Warp-MMA tree conv: D[64(mh), 32nodes] = W * G^T via mma.sync m16n8k16 fp16/f32.
// Grid (148, mh=2, e=2); CTA 256 thr = 8 warps (4m x 2n), warp tile M=16 x N=16.
// W fragment-packed half2 in smem (LDS.128); G (fp16) double-buffered via cp.async
// from pre-rounded sources (g_featsT / g_h).
// SECOND=false: store raw out1 (fp32) + stats1.  SECOND=true: stats2 + per-(b,o) max.
// =================================================================================
template<int KD, bool SECOND>
__global__ void __launch_bounds__(256, 2) conv_mma_kernel(
    const int* __restrict__ children,
    const float* __restrict__ Wl, const float* __restrict__ bl,
    const float* __restrict__ Wp, const float* __restrict__ bp)
{
    constexpr int NT    = 32;             // nodes per tile
    constexpr int CPC   = KD / 3;         // halves per child slot (64 / 128)
    constexpr int KDPH  = KD + 8;         // padded G row stride (halves) -> word stride mod 32 == 4
    constexpr int NCH   = KD / 16;        // k-chunks (12 / 24)
    constexpr int UNITS = CPC / 8;        // 16B cp.async units per child slot (8 / 16)
    constexpr int TPB   = TNODE / NT;     // 128 tiles per example
    constexpr int TILES = BATCH * TPB;    // 8192 per (e, mh)
    constexpr int GBYTES = NT * KDPH * 2; // bytes per G buffer

    const int e  = blockIdx.z;
    const int mh = blockIdx.y;
    const int per = (TILES + 147) / 148;
    const int t0 = blockIdx.x * per;
    const int t1 = min(TILES, t0 + per);
    if (t0 >= t1) return;

    extern __shared__ char smem[];
    uint32_t* s_W    = (uint32_t*)smem;                    // 32*KD uint32 (half2 pairs), fragment-packed
    __half*   s_G    = (__half*)(smem + 32 * KD * 4);      // 2 * NT * KDPH halves
    float*    s_bias = (float*)(smem + 32 * KD * 4 + 2 * GBYTES);  // 64
    const uint32_t g_u32 = smem_u32(s_G);

    const int tid = threadIdx.x;
    const int wid = tid >> 5, l = tid & 31;
    const int mp = wid >> 1, np = wid & 1;     // 4 m-warps x 2 n-warps

    // ---- fill W fragment-packed fp16 + bias ----
    // idx32 = (mp*NCH + q)*128 + lane*4 + reg ; each uint32 = half2 {k0, k0+1}
    //   reg&1 -> m+8 ; reg>>1 -> k+8
    //   m_loc = mp*16 + (lane>>2) + ((reg&1)<<3)
    //   k0    = q*16 + (lane&3)*2 + ((reg>>1)<<3)
    const float* Wg = e ? Wp : Wl;
    const float* bg = e ? bp : bl;
    for (int idx = tid; idx < 32 * KD; idx += 256) {
        int reg  = idx & 3;
        int lane = (idx >> 2) & 31;
        int rest = idx >> 7;
        int q    = rest % NCH;
        int mpp  = rest / NCH;
        int m_loc = mpp * 16 + (lane >> 2) + ((reg & 1) << 3);
        int k0    = q * 16 + (lane & 3) * 2 + ((reg >> 1) << 3);
        int c0 = k0 % CPC, k30 = k0 / CPC;
        int k1 = k0 + 1;
        int c1 = k1 % CPC, k31 = k1 / CPC;
        const float* wrow = Wg + (size_t)(mh * 64 + m_loc) * KD;
        __half2 h = __floats2half2_rn(wrow[c0 * 3 + k30], wrow[c1 * 3 + k31]);
        s_W[idx] = *(uint32_t*)&h;
    }
    if (tid < 64) s_bias[tid] = bg[mh * 64 + tid];

    // ---- gather issue: raw cp.async of pre-rounded fp16 rows ----
    auto issue_gather = [&](int t, int buf) {
        int b = t >> 7;                       // / TPB
        int tl = t & 127;
        const int* chb = children + (size_t)b * 3 * TNODE + 3 * tl * NT;
        const __half* sb = SECOND ? g_h[e] + (size_t)b * NNODE * HID
                                  : g_featsT[e] + (size_t)b * NNODE * CIN;
        uint32_t gd = g_u32 + (uint32_t)buf * GBYTES;
#pragma unroll
        for (int idx = tid; idx < 3 * NT * UNITS; idx += 256) {
            int row = idx / UNITS;
            int u   = idx & (UNITS - 1);
            int i = row / 3, k3 = row - i * 3;
            int child = __ldg(chb + row);
            cp_async16(gd + (uint32_t)(i * KDPH * 2 + k3 * CPC * 2 + u * 16),
                       sb + (size_t)child * CPC + u * 8);
        }
        cp_commit();
    };

    issue_gather(t0, 0);
    if (t0 + 1 < t1) issue_gather(t0 + 1, 1);

    for (int t = t0; t < t1; ++t) {
        int buf = (t - t0) & 1;
        if (t + 1 < t1) cp_wait<1>(); else cp_wait<0>();
        __syncthreads();

        // ---- MMA: warp tile M=16 x N=16, K=KD ----
        float d[2][4];
#pragma unroll
        for (int nt = 0; nt < 2; ++nt)
#pragma unroll
            for (int r = 0; r < 4; ++r) d[nt][r] = 0.f;

        const __half* Gb = s_G + buf * (NT * KDPH);
        const int nrow0 = np * 16 + (l >> 2);
        const int kbyte = (l & 3) * 4;        // (l&3)*2 halves
#pragma unroll 4
        for (int q = 0; q < NCH; ++q) {
            uint4 a = ((const uint4*)(s_W + ((mp * NCH + q) << 7)))[l];
            const char* gp0 = (const char*)Gb + (size_t)(nrow0    ) * KDPH * 2 + q * 32 + kbyte;
            const char* gp1 = (const char*)Gb + (size_t)(nrow0 + 8) * KDPH * 2 + q * 32 + kbyte;
            uint32_t b00 = *(const uint32_t*)(gp0);
            uint32_t b01 = *(const uint32_t*)(gp0 + 16);
            uint32_t b10 = *(const uint32_t*)(gp1);
            uint32_t b11 = *(const uint32_t*)(gp1 + 16);
            mma_f16(d[0], a, b00, b01);
            mma_f16(d[1], a, b10, b11);
        }

        // ---- epilogue ----
        int b = t >> 7, tl = t & 127;
        int n0 = 1 + tl * NT;
        float bb[2];
#pragma unroll
        for (int h = 0; h < 2; ++h)
            bb[h] = s_bias[mp * 16 + (l >> 2) + h * 8];

        float ls = 0.f, lss = 0.f;
        if (SECOND) {
            float mx[2] = {-3.4e38f, -3.4e38f};
#pragma unroll
            for (int nt = 0; nt < 2; ++nt)
#pragma unroll
                for (int r = 0; r < 4; ++r) {
                    float v = d[nt][r] + bb[r >> 1];
                    ls += v; lss += v * v;
                    mx[r >> 1] = fmaxf(mx[r >> 1], v);
                }
#pragma unroll
            for (int h = 0; h < 2; ++h) {
                float m = mx[h];
                m = fmaxf(m, __shfl_xor_sync(0xffffffffu, m, 1));
                m = fmaxf(m, __shfl_xor_sync(0xffffffffu, m, 2));
                if ((l & 3) == 0) {
                    int mg = mh * 64 + mp * 16 + (l >> 2) + h * 8;
                    atomicMax(&g_max2[e][b][mg], f2ord(m));
                }
            }
        } else {
            float* ob = g_out1[e] + ((size_t)b * NNODE + n0) * HID + mh * 64;
#pragma unroll
            for (int nt = 0; nt < 2; ++nt)
#pragma unroll
                for (int r = 0; r < 4; ++r) {
                    float v = d[nt][r] + bb[r >> 1];
                    int n_loc = np * 16 + nt * 8 + (l & 3) * 2 + (r & 1);
                    int m_loc = mp * 16 + (l >> 2) + (r >> 1) * 8;
                    ob[(size_t)n_loc * HID + m_loc] = v;
                    ls += v; lss += v * v;
                }
        }
#pragma unroll
        for (int off = 16; off; off >>= 1) {
            ls  += __shfl_xor_sync(0xffffffffu, ls, off);
            lss += __shfl_xor_sync(0xffffffffu, lss, off);
        }
        if (l == 0) {
            float* st = SECOND ? g_stats2[e][b] : g_stats1[e][b];
            atomicAdd(&st[0], ls);
            atomicAdd(&st[1], lss);
        }

        __syncthreads();                      // all warps done reading this buffer
        if (t + 2 < t1) issue_gather(t + 2, buf);
    }
}

// ---------------- finalize: LN2+relu on max, concat, mu/logvar GEMVs ---------------
__global__ void finalize_kernel(const float* __restrict__ Wmu, const float* __restrict__ bmu,
                                const float* __restrict__ Wlv, const float* __restrict__ blv,
                                float* __restrict__ out)
{
    __shared__ float comb[2 * HID];
    int b = blockIdx.x, tid = threadIdx.x;
    const float cntv = (float)(HID * NNODE);
#pragma unroll
    for (int e = 0; e < 2; ++e) {
        float st  = g_stats2[e][b][0];
        float sst = g_stats2[e][b][1];
        float mean = st / cntv;
        float var  = (sst - st * st / cntv) / (cntv - 1.f);
        float inv  = 1.f / (sqrtf(var) + EPSV);
        if (tid < HID) {
            float m = ord2f(g_max2[e][b][tid]);
            comb[e * HID + tid] = fmaxf(0.f, (m - mean) * inv);
        }
    }
    __syncthreads();
    if (tid < 64) {
        float acc = bmu[tid];
        for (int j = 0; j < 2 * HID; ++j) acc += Wmu[tid * 2 * HID + j] * comb[j];
        out[b * LAT + tid] = acc;
    } else if (tid < 128) {
        int t = tid - 64;
        float acc = blv[t];
        for (int j = 0; j < 2 * HID; ++j) acc += Wlv[t * 2 * HID + j] * comb[j];
        out[BATCH * LAT + b * LAT + t] = acc;
    }
}

// -------------------------------- launch --------------------------------
extern "C" void kernel_launch(void* const* d_in, const int* in_sizes, int n_in,
                              void* d_out, int out_size)
{
    const float* lf  = (const float*)d_in[0];
    const float* pf  = (const float*)d_in[1];
    const int*   ch  = (const int*)d_in[2];
    const float* Wl1 = (const float*)d_in[3];  const float* bl1 = (const float*)d_in[4];
    const float* Wl2 = (const float*)d_in[5];  const float* bl2 = (const float*)d_in[6];
    const float* Wp1 = (const float*)d_in[7];  const float* bp1 = (const float*)d_in[8];
    const float* Wp2 = (const float*)d_in[9];  const float* bp2 = (const float*)d_in[10];
    const float* Wmu = (const float*)d_in[11]; const float* bmu = (const float*)d_in[12];
    const float* Wlv = (const float*)d_in[13]; const float* blv = (const float*)d_in[14];
    float* out = (float*)d_out;

    // dynamic smem: W(32*KD u32) + 2 G buffers (NT*(KD+8) halves) + bias(64 f32)
    const int SMEM1 = 32 * 192 * 4 + 2 * 32 * (192 + 8) * 2 + 256;   //  50,432 B
    const int SMEM2 = 32 * 384 * 4 + 2 * 32 * (384 + 8) * 2 + 256;   //  99,584 B (2 CTAs/SM)
    cudaFuncSetAttribute(conv_mma_kernel<192, false>,
                         cudaFuncAttributeMaxDynamicSharedMemorySize, SMEM1);
    cudaFuncSetAttribute(conv_mma_kernel<384, true>,
                         cudaFuncAttributeMaxDynamicSharedMemorySize, SMEM2);

    init_kernel<<<(2 * BATCH * HID + 255) / 256, 256>>>();
    transpose_kernel<<<dim3((NNODE + 31) / 32, CIN / 32, 2 * BATCH), dim3(32, 8)>>>(lf, pf);
    conv_mma_kernel<192, false><<<dim3(148, 2, 2), 256, SMEM1>>>(ch, Wl1, bl1, Wp1, bp1);
    transform_kernel<<<dim3((NNODE * HID / 4 + 255) / 256, 2 * BATCH), 256>>>();
    conv_mma_kernel<384, true ><<<dim3(148, 2, 2), 256, SMEM2>>>(ch, Wl2, bl2, Wp2, bp2);
    finalize_kernel<<<BATCH, 128>>>(Wmu, bmu, Wlv, blv, out);
}

// round 14
// speedup vs baseline: 1.8734x; 1.1345x over previous
#include <cuda_runtime.h>
#include <cuda_fp16.h>
#include <math.h>
#include <stdint.h>

#define BATCH 64
#define CIN   64
#define NNODE 4097
#define TNODE 4096
#define HID   128
#define LAT   64
#define EPSV  1e-5f

// -------- scratch (device globals; no allocation allowed) ----------
__device__ __half   g_featsT[2][(size_t)BATCH * NNODE * CIN];   // (B,N,C), fp16
__device__ __half   g_out1  [2][(size_t)BATCH * NNODE * HID];   // conv1 raw output, fp16 (node0 = 0)
__device__ __half   g_h     [2][(size_t)BATCH * NNODE * HID];   // fp16(relu(LN(out1)))
__device__ float    g_stats1[2][BATCH][2];                      // sum, sumsq of conv1 raw (fp32)
__device__ float    g_stats2[2][BATCH][2];                      // sum, sumsq of conv2 raw
__device__ unsigned g_max2  [2][BATCH][HID];                    // per (b,o) max of conv2 raw (ordered)

// monotone float<->uint encoding so atomicMax(unsigned) == float max
__device__ __forceinline__ unsigned f2ord(float f) {
    unsigned u = __float_as_uint(f);
    return (u & 0x80000000u) ? ~u : (u | 0x80000000u);
}
__device__ __forceinline__ float ord2f(unsigned u) {
    return __uint_as_float((u & 0x80000000u) ? (u ^ 0x80000000u) : ~u);
}

// ---------------- small PTX helpers (all portable, sm_80+) ----------------
__device__ __forceinline__ uint32_t smem_u32(const void* p) {
    uint32_t a;
    asm("{ .reg .u64 t; cvta.to.shared.u64 t, %1; cvt.u32.u64 %0, t; }" : "=r"(a) : "l"(p));
    return a;
}
__device__ __forceinline__ void cp_async16(uint32_t dst, const void* src) {
    asm volatile("cp.async.cg.shared.global [%0], [%1], 16;" :: "r"(dst), "l"(src));
}
__device__ __forceinline__ void cp_commit() {
    asm volatile("cp.async.commit_group;" ::: "memory");
}
template<int N> __device__ __forceinline__ void cp_wait() {
    asm volatile("cp.async.wait_group %0;" :: "n"(N) : "memory");
}
// D += A(16x16) * B(16x8), fp16 inputs, fp32 accumulate
__device__ __forceinline__ void mma_f16(float* d, const uint4& a, uint32_t b0, uint32_t b1) {
    asm volatile(
        "mma.sync.aligned.m16n8k16.row.col.f32.f16.f16.f32 "
        "{%0,%1,%2,%3}, {%4,%5,%6,%7}, {%8,%9}, {%0,%1,%2,%3};\n"
        : "+f"(d[0]), "+f"(d[1]), "+f"(d[2]), "+f"(d[3])
        : "r"(a.x), "r"(a.y), "r"(a.z), "r"(a.w), "r"(b0), "r"(b1));
}

// ---------------- init: zero stats, node-0 rows, max buffers ----------------
__global__ void init_kernel() {
    int i = blockIdx.x * blockDim.x + threadIdx.x;
    if (i < 2 * BATCH * HID) {
        int e = i / (BATCH * HID);
        int r = i % (BATCH * HID);
        int b = r / HID, o = r % HID;
        g_max2[e][b][o] = 0x80000000u;                            // encodes 0.0f
        g_out1[e][(size_t)b * NNODE * HID + o] = __float2half(0.f);
        g_h[e][(size_t)b * NNODE * HID + o] = __float2half(0.f);
    }
    if (i < 2 * BATCH) {
        int e = i / BATCH, b = i % BATCH;
        g_stats1[e][b][0] = 0.f; g_stats1[e][b][1] = 0.f;
        g_stats2[e][b][0] = 0.f; g_stats2[e][b][1] = 0.f;
    }
}

// ---------------- transpose (B,C,N) -> (B,N,C), rounding to fp16 -------------
__global__ void transpose_kernel(const float* __restrict__ lf, const float* __restrict__ pf) {
    __shared__ float tile[32][33];
    int e = blockIdx.z >> 6;
    int b = blockIdx.z & 63;
    const float* src = e ? pf : lf;
    int n0 = blockIdx.x << 5, c0 = blockIdx.y << 5;
    int tx = threadIdx.x, ty = threadIdx.y;
#pragma unroll
    for (int i = 0; i < 32; i += 8) {
        int n = n0 + tx;
        if (n < NNODE) tile[ty + i][tx] = src[((size_t)b * CIN + c0 + ty + i) * NNODE + n];
    }
    __syncthreads();
#pragma unroll
    for (int i = 0; i < 32; i += 8) {
        int n = n0 + ty + i;
        if (n < NNODE)
            g_featsT[e][((size_t)b * NNODE + n) * CIN + c0 + tx] = __float2half_rn(tile[tx][ty + i]);
    }
}

// ---------------- transform: g_h = fp16(relu(LN1(g_out1))), fp16 in/out ----------------
__global__ void transform_kernel() {
    const int P8 = NNODE * HID / 8;            // 65552 uint4 (8 halves) per (e,b)
    int i = blockIdx.x * blockDim.x + threadIdx.x;
    if (i >= P8) return;
    int e = blockIdx.y >> 6, b = blockIdx.y & 63;
    float st = g_stats1[e][b][0], sst = g_stats1[e][b][1];
    const float cnt = (float)(HID * NNODE);
    float mean = st / cnt;
    float var = (sst - st * st / cnt) / (cnt - 1.f);
    float inv = 1.f / (sqrtf(var) + EPSV);
    uint4 x = ((const uint4*)(g_out1[e] + (size_t)b * NNODE * HID))[i];
    uint4 y;
#pragma unroll
    for (int j = 0; j < 4; ++j) {
        uint32_t w = (&x.x)[j];
        __half2 h = *(__half2*)&w;
        float2 f = __half22float2(h);
        __half2 o = __floats2half2_rn(fmaxf(0.f, (f.x - mean) * inv),
                                      fmaxf(0.f, (f.y - mean) * inv));
        (&y.x)[j] = *(uint32_t*)&o;
    }
    ((uint4*)(g_h[e] + (size_t)b * NNODE * HID))[i] = y;
}

// =================================================================================
// Warp-MMA tree conv: D[64(mh), 32nodes] = W * G^T via mma.sync m16n8k16 fp16/f32.
// Grid (148, mh=2, e=2); CTA 256 thr = 8 warps (4m x 2n), warp tile M=16 x N=16.
// A (weights) held ENTIRELY in registers (4*NCH u32 per thread), loaded once from
// global; smem holds only the double-buffered gathered G tile (cp.async) -> the
// crossbar now moves only B-fragment bytes (2x fewer than R13).
// SECOND=false: store raw out1 (fp16) + stats1.  SECOND=true: stats2 + per-(b,o) max.
// =================================================================================
template<int KD, bool SECOND>
__global__ void __launch_bounds__(256, 2) conv_mma_kernel(
    const int* __restrict__ children,
    const float* __restrict__ Wl, const float* __restrict__ bl,
    const float* __restrict__ Wp, const float* __restrict__ bp)
{
    constexpr int NT    = 32;             // nodes per tile
    constexpr int CPC   = KD / 3;         // halves per child slot (64 / 128)
    constexpr int KDPH  = KD + 8;         // padded G row stride (halves) -> conflict-free
    constexpr int NCH   = KD / 16;        // k-chunks (12 / 24)
    constexpr int UNITS = CPC / 8;        // 16B cp.async units per child slot (8 / 16)
    constexpr int TPB   = TNODE / NT;     // 128 tiles per example
    constexpr int TILES = BATCH * TPB;    // 8192 per (e, mh)
    constexpr int GBYTES = NT * KDPH * 2; // bytes per G buffer

    const int e  = blockIdx.z;
    const int mh = blockIdx.y;
    const int per = (TILES + 147) / 148;
    const int t0 = blockIdx.x * per;
    const int t1 = min(TILES, t0 + per);
    if (t0 >= t1) return;

    extern __shared__ char smem[];
    __half* s_G    = (__half*)smem;                       // 2 * NT * KDPH halves
    float*  s_bias = (float*)(smem + 2 * GBYTES);         // 64
    const uint32_t g_u32 = smem_u32(s_G);

    const int tid = threadIdx.x;
    const int wid = tid >> 5, l = tid & 31;
    const int mp = wid >> 1, np = wid & 1;     // 4 m-warps x 2 n-warps

    // ---- load A fragments into registers (once per CTA; scattered LDG, L2-served) ----
    const float* Wg = e ? Wp : Wl;
    const float* bg = e ? bp : bl;
    uint4 afrag[NCH];
    {
        const int mbase = mh * 64 + mp * 16 + (l >> 2);
#pragma unroll
        for (int q = 0; q < NCH; ++q) {
            uint32_t r[4];
#pragma unroll
            for (int reg = 0; reg < 4; ++reg) {
                int m_loc = mbase + ((reg & 1) << 3);
                int k0 = q * 16 + (l & 3) * 2 + ((reg >> 1) << 3);
                int c = k0 % CPC, k3 = k0 / CPC;     // k0 even, CPC even -> pair same k3
                const float* wr = Wg + (size_t)m_loc * KD;
                __half2 h = __floats2half2_rn(__ldg(wr + c * 3 + k3),
                                              __ldg(wr + (c + 1) * 3 + k3));
                r[reg] = *(uint32_t*)&h;
            }
            afrag[q] = make_uint4(r[0], r[1], r[2], r[3]);
        }
    }
    if (tid < 64) s_bias[tid] = bg[mh * 64 + tid];

    // ---- gather issue: raw cp.async of pre-rounded fp16 rows ----
    auto issue_gather = [&](int t, int buf) {
        int b = t >> 7;                       // / TPB
        int tl = t & 127;
        const int* chb = children + (size_t)b * 3 * TNODE + 3 * tl * NT;
        const __half* sb = SECOND ? g_h[e] + (size_t)b * NNODE * HID
                                  : g_featsT[e] + (size_t)b * NNODE * CIN;
        uint32_t gd = g_u32 + (uint32_t)buf * GBYTES;
#pragma unroll
        for (int idx = tid; idx < 3 * NT * UNITS; idx += 256) {
            int row = idx / UNITS;
            int u   = idx & (UNITS - 1);
            int i = row / 3, k3 = row - i * 3;
            int child = __ldg(chb + row);
            cp_async16(gd + (uint32_t)(i * KDPH * 2 + k3 * CPC * 2 + u * 16),
                       sb + (size_t)child * CPC + u * 8);
        }
        cp_commit();
    };

    issue_gather(t0, 0);
    if (t0 + 1 < t1) issue_gather(t0 + 1, 1);

    for (int t = t0; t < t1; ++t) {
        int buf = (t - t0) & 1;
        if (t + 1 < t1) cp_wait<1>(); else cp_wait<0>();
        __syncthreads();

        // ---- MMA: warp tile M=16 x N=16, K=KD; A from registers, B from smem ----
        float d[2][4];
#pragma unroll
        for (int nt = 0; nt < 2; ++nt)
#pragma unroll
            for (int r = 0; r < 4; ++r) d[nt][r] = 0.f;

        const __half* Gb = s_G + buf * (NT * KDPH);
        const int nrow0 = np * 16 + (l >> 2);
        const int kbyte = (l & 3) * 4;
#pragma unroll
        for (int q = 0; q < NCH; ++q) {
            const char* gp0 = (const char*)Gb + (size_t)(nrow0    ) * KDPH * 2 + q * 32 + kbyte;
            const char* gp1 = (const char*)Gb + (size_t)(nrow0 + 8) * KDPH * 2 + q * 32 + kbyte;
            uint32_t b00 = *(const uint32_t*)(gp0);
            uint32_t b01 = *(const uint32_t*)(gp0 + 16);
            uint32_t b10 = *(const uint32_t*)(gp1);
            uint32_t b11 = *(const uint32_t*)(gp1 + 16);
            mma_f16(d[0], afrag[q], b00, b01);
            mma_f16(d[1], afrag[q], b10, b11);
        }

        // ---- epilogue ----
        int b = t >> 7, tl = t & 127;
        int n0 = 1 + tl * NT;
        float bb[2];
#pragma unroll
        for (int h = 0; h < 2; ++h)
            bb[h] = s_bias[mp * 16 + (l >> 2) + h * 8];

        float ls = 0.f, lss = 0.f;
        if (SECOND) {
            float mx[2] = {-3.4e38f, -3.4e38f};
#pragma unroll
            for (int nt = 0; nt < 2; ++nt)
#pragma unroll
                for (int r = 0; r < 4; ++r) {
                    float v = d[nt][r] + bb[r >> 1];
                    ls += v; lss += v * v;
                    mx[r >> 1] = fmaxf(mx[r >> 1], v);
                }
#pragma unroll
            for (int h = 0; h < 2; ++h) {
                float m = mx[h];
                m = fmaxf(m, __shfl_xor_sync(0xffffffffu, m, 1));
                m = fmaxf(m, __shfl_xor_sync(0xffffffffu, m, 2));
                if ((l & 3) == 0) {
                    int mg = mh * 64 + mp * 16 + (l >> 2) + h * 8;
                    atomicMax(&g_max2[e][b][mg], f2ord(m));
                }
            }
        } else {
            __half* ob = g_out1[e] + ((size_t)b * NNODE + n0) * HID + mh * 64;
#pragma unroll
            for (int nt = 0; nt < 2; ++nt)
#pragma unroll
                for (int r = 0; r < 4; ++r) {
                    float v = d[nt][r] + bb[r >> 1];
                    int n_loc = np * 16 + nt * 8 + (l & 3) * 2 + (r & 1);
                    int m_loc = mp * 16 + (l >> 2) + (r >> 1) * 8;
                    ob[(size_t)n_loc * HID + m_loc] = __float2half_rn(v);
                    ls += v; lss += v * v;
                }
        }
#pragma unroll
        for (int off = 16; off; off >>= 1) {
            ls  += __shfl_xor_sync(0xffffffffu, ls, off);
            lss += __shfl_xor_sync(0xffffffffu, lss, off);
        }
        if (l == 0) {
            float* st = SECOND ? g_stats2[e][b] : g_stats1[e][b];
            atomicAdd(&st[0], ls);
            atomicAdd(&st[1], lss);
        }

        __syncthreads();                      // all warps done reading this buffer
        if (t + 2 < t1) issue_gather(t + 2, buf);
    }
}

// ---------------- finalize: LN2+relu on max, concat, mu/logvar GEMVs ---------------
__global__ void finalize_kernel(const float* __restrict__ Wmu, const float* __restrict__ bmu,
                                const float* __restrict__ Wlv, const float* __restrict__ blv,
                                float* __restrict__ out)
{
    __shared__ float comb[2 * HID];
    int b = blockIdx.x, tid = threadIdx.x;
    const float cntv = (float)(HID * NNODE);
#pragma unroll
    for (int e = 0; e < 2; ++e) {
        float st  = g_stats2[e][b][0];
        float sst = g_stats2[e][b][1];
        float mean = st / cntv;
        float var  = (sst - st * st / cntv) / (cntv - 1.f);
        float inv  = 1.f / (sqrtf(var) + EPSV);
        if (tid < HID) {
            float m = ord2f(g_max2[e][b][tid]);
            comb[e * HID + tid] = fmaxf(0.f, (m - mean) * inv);
        }
    }
    __syncthreads();
    if (tid < 64) {
        float acc = bmu[tid];
        for (int j = 0; j < 2 * HID; ++j) acc += Wmu[tid * 2 * HID + j] * comb[j];
        out[b * LAT + tid] = acc;
    } else if (tid < 128) {
        int t = tid - 64;
        float acc = blv[t];
        for (int j = 0; j < 2 * HID; ++j) acc += Wlv[t * 2 * HID + j] * comb[j];
        out[BATCH * LAT + b * LAT + t] = acc;
    }
}

// -------------------------------- launch --------------------------------
extern "C" void kernel_launch(void* const* d_in, const int* in_sizes, int n_in,
                              void* d_out, int out_size)
{
    const float* lf  = (const float*)d_in[0];
    const float* pf  = (const float*)d_in[1];
    const int*   ch  = (const int*)d_in[2];
    const float* Wl1 = (const float*)d_in[3];  const float* bl1 = (const float*)d_in[4];
    const float* Wl2 = (const float*)d_in[5];  const float* bl2 = (const float*)d_in[6];
    const float* Wp1 = (const float*)d_in[7];  const float* bp1 = (const float*)d_in[8];
    const float* Wp2 = (const float*)d_in[9];  const float* bp2 = (const float*)d_in[10];
    const float* Wmu = (const float*)d_in[11]; const float* bmu = (const float*)d_in[12];
    const float* Wlv = (const float*)d_in[13]; const float* blv = (const float*)d_in[14];
    float* out = (float*)d_out;

    // dynamic smem: 2 G buffers (NT*(KD+8) halves) + bias(64 f32)
    const int SMEM1 = 2 * 32 * (192 + 8) * 2 + 256;   // 25,856 B
    const int SMEM2 = 2 * 32 * (384 + 8) * 2 + 256;   // 50,432 B
    cudaFuncSetAttribute(conv_mma_kernel<192, false>,
                         cudaFuncAttributeMaxDynamicSharedMemorySize, SMEM1);
    cudaFuncSetAttribute(conv_mma_kernel<384, true>,
                         cudaFuncAttributeMaxDynamicSharedMemorySize, SMEM2);

    init_kernel<<<(2 * BATCH * HID + 255) / 256, 256>>>();
    transpose_kernel<<<dim3((NNODE + 31) / 32, CIN / 32, 2 * BATCH), dim3(32, 8)>>>(lf, pf);
    conv_mma_kernel<192, false><<<dim3(148, 2, 2), 256, SMEM1>>>(ch, Wl1, bl1, Wp1, bp1);
    transform_kernel<<<dim3((NNODE * HID / 8 + 255) / 256, 2 * BATCH), 256>>>();
    conv_mma_kernel<384, true ><<<dim3(148, 2, 2), 256, SMEM2>>>(ch, Wl2, bl2, Wp2, bp2);
    finalize_kernel<<<BATCH, 128>>>(Wmu, bmu, Wlv, blv, out);
}

// round 15
// speedup vs baseline: 1.9120x; 1.0206x over previous
#include <cuda_runtime.h>
#include <cuda_fp16.h>
#include <math.h>
#include <stdint.h>

#define BATCH 64
#define CIN   64
#define NNODE 4097
#define TNODE 4096
#define HID   128
#define LAT   64
#define EPSV  1e-5f

// -------- scratch (device globals; no allocation allowed) ----------
__device__ __half   g_featsT[2][(size_t)BATCH * NNODE * CIN];   // (B,N,C), fp16
__device__ __half   g_out1  [2][(size_t)BATCH * NNODE * HID];   // conv1 raw output, fp16 (node0 = 0)
__device__ __half   g_h     [2][(size_t)BATCH * NNODE * HID];   // fp16(relu(LN(out1)))
__device__ float    g_stats1[2][BATCH][2];                      // sum, sumsq of conv1 raw (fp32)
__device__ float    g_stats2[2][BATCH][2];                      // sum, sumsq of conv2 raw
__device__ unsigned g_max2  [2][BATCH][HID];                    // per (b,o) max of conv2 raw (ordered)

// monotone float<->uint encoding so atomicMax(unsigned) == float max
__device__ __forceinline__ unsigned f2ord(float f) {
    unsigned u = __float_as_uint(f);
    return (u & 0x80000000u) ? ~u : (u | 0x80000000u);
}
__device__ __forceinline__ float ord2f(unsigned u) {
    return __uint_as_float((u & 0x80000000u) ? (u ^ 0x80000000u) : ~u);
}

// ---------------- small PTX helpers (all portable, sm_80+) ----------------
__device__ __forceinline__ uint32_t smem_u32(const void* p) {
    uint32_t a;
    asm("{ .reg .u64 t; cvta.to.shared.u64 t, %1; cvt.u32.u64 %0, t; }" : "=r"(a) : "l"(p));
    return a;
}
__device__ __forceinline__ void cp_async16(uint32_t dst, const void* src) {
    asm volatile("cp.async.cg.shared.global [%0], [%1], 16;" :: "r"(dst), "l"(src));
}
__device__ __forceinline__ void cp_commit() {
    asm volatile("cp.async.commit_group;" ::: "memory");
}
template<int N> __device__ __forceinline__ void cp_wait() {
    asm volatile("cp.async.wait_group %0;" :: "n"(N) : "memory");
}
// D += A(16x16) * B(16x8), fp16 inputs, fp32 accumulate
__device__ __forceinline__ void mma_f16(float* d, const uint4& a, uint32_t b0, uint32_t b1) {
    asm volatile(
        "mma.sync.aligned.m16n8k16.row.col.f32.f16.f16.f32 "
        "{%0,%1,%2,%3}, {%4,%5,%6,%7}, {%8,%9}, {%0,%1,%2,%3};\n"
        : "+f"(d[0]), "+f"(d[1]), "+f"(d[2]), "+f"(d[3])
        : "r"(a.x), "r"(a.y), "r"(a.z), "r"(a.w), "r"(b0), "r"(b1));
}
// load 4 m8n8 b16 matrices (B fragments for both n-halves of the warp tile)
__device__ __forceinline__ void ldsm_x4(uint32_t& r0, uint32_t& r1, uint32_t& r2, uint32_t& r3,
                                        uint32_t addr) {
    asm volatile("ldmatrix.sync.aligned.m8n8.x4.shared.b16 {%0,%1,%2,%3}, [%4];"
                 : "=r"(r0), "=r"(r1), "=r"(r2), "=r"(r3) : "r"(addr));
}

// ---------------- init: zero stats, node-0 rows, max buffers ----------------
__global__ void init_kernel() {
    int i = blockIdx.x * blockDim.x + threadIdx.x;
    if (i < 2 * BATCH * HID) {
        int e = i / (BATCH * HID);
        int r = i % (BATCH * HID);
        int b = r / HID, o = r % HID;
        g_max2[e][b][o] = 0x80000000u;                            // encodes 0.0f
        g_out1[e][(size_t)b * NNODE * HID + o] = __float2half(0.f);
        g_h[e][(size_t)b * NNODE * HID + o] = __float2half(0.f);
    }
    if (i < 2 * BATCH) {
        int e = i / BATCH, b = i % BATCH;
        g_stats1[e][b][0] = 0.f; g_stats1[e][b][1] = 0.f;
        g_stats2[e][b][0] = 0.f; g_stats2[e][b][1] = 0.f;
    }
}

// ---------------- transpose (B,C,N) -> (B,N,C), rounding to fp16 -------------
__global__ void transpose_kernel(const float* __restrict__ lf, const float* __restrict__ pf) {
    __shared__ float tile[32][33];
    int e = blockIdx.z >> 6;
    int b = blockIdx.z & 63;
    const float* src = e ? pf : lf;
    int n0 = blockIdx.x << 5, c0 = blockIdx.y << 5;
    int tx = threadIdx.x, ty = threadIdx.y;
#pragma unroll
    for (int i = 0; i < 32; i += 8) {
        int n = n0 + tx;
        if (n < NNODE) tile[ty + i][tx] = src[((size_t)b * CIN + c0 + ty + i) * NNODE + n];
    }
    __syncthreads();
#pragma unroll
    for (int i = 0; i < 32; i += 8) {
        int n = n0 + ty + i;
        if (n < NNODE)
            g_featsT[e][((size_t)b * NNODE + n) * CIN + c0 + tx] = __float2half_rn(tile[tx][ty + i]);
    }
}

// ---------------- transform: g_h = fp16(relu(LN1(g_out1))), fp16 in/out ----------------
__global__ void transform_kernel() {
    const int P8 = NNODE * HID / 8;            // 65552 uint4 (8 halves) per (e,b)
    int i = blockIdx.x * blockDim.x + threadIdx.x;
    if (i >= P8) return;
    int e = blockIdx.y >> 6, b = blockIdx.y & 63;
    float st = g_stats1[e][b][0], sst = g_stats1[e][b][1];
    const float cnt = (float)(HID * NNODE);
    float mean = st / cnt;
    float var = (sst - st * st / cnt) / (cnt - 1.f);
    float inv = 1.f / (sqrtf(var) + EPSV);
    uint4 x = ((const uint4*)(g_out1[e] + (size_t)b * NNODE * HID))[i];
    uint4 y;
#pragma unroll
    for (int j = 0; j < 4; ++j) {
        uint32_t w = (&x.x)[j];
        __half2 h = *(__half2*)&w;
        float2 f = __half22float2(h);
        __half2 o = __floats2half2_rn(fmaxf(0.f, (f.x - mean) * inv),
                                      fmaxf(0.f, (f.y - mean) * inv));
        (&y.x)[j] = *(uint32_t*)&o;
    }
    ((uint4*)(g_h[e] + (size_t)b * NNODE * HID))[i] = y;
}

// =================================================================================
// Warp-MMA tree conv: D[64(mh), 32nodes] = W * G^T via mma.sync m16n8k16 fp16/f32.
// Grid (148, mh=2, e=2); CTA 256 thr = 8 warps (4m x 2n), warp tile M=16 x N=16.
// A (weights) in registers; B fragments loaded with ldmatrix.x4 (1 instr per
// k-chunk, conflict-free); G double-buffered via cp.async.
// SECOND=false: out1 staged in smem -> coalesced STG.128 + stats1.
// SECOND=true : stats2 + per-(b,o) max (no output materialized).
// =================================================================================
template<int KD, bool SECOND>
__global__ void __launch_bounds__(256, 2) conv_mma_kernel(
    const int* __restrict__ children,
    const float* __restrict__ Wl, const float* __restrict__ bl,
    const float* __restrict__ Wp, const float* __restrict__ bp)
{
    constexpr int NT    = 32;             // nodes per tile
    constexpr int CPC   = KD / 3;         // halves per child slot (64 / 128)
    constexpr int KDPH  = KD + 8;         // padded G row stride (halves): word stride mod 32 == 4
    constexpr int NCH   = KD / 16;        // k-chunks (12 / 24)
    constexpr int UNITS = CPC / 8;        // 16B cp.async units per child slot (8 / 16)
    constexpr int TPB   = TNODE / NT;     // 128 tiles per example
    constexpr int TILES = BATCH * TPB;    // 8192 per (e, mh)
    constexpr int GBYTES = NT * KDPH * 2; // bytes per G buffer
    constexpr int SROW  = 72;             // stage row stride (halves): 144B, 16B-aligned, conflict-free

    const int e  = blockIdx.z;
    const int mh = blockIdx.y;
    const int per = (TILES + 147) / 148;
    const int t0 = blockIdx.x * per;
    const int t1 = min(TILES, t0 + per);
    if (t0 >= t1) return;

    extern __shared__ char smem[];
    __half* s_stage = (__half*)smem;                      // 32*SROW halves (conv1 output staging)
    __half* s_G     = (__half*)(smem + 32 * SROW * 2);    // 2 * NT * KDPH halves
    float*  s_bias  = (float*)(smem + 32 * SROW * 2 + 2 * GBYTES);  // 64
    const uint32_t g_u32 = smem_u32(s_G);

    const int tid = threadIdx.x;
    const int wid = tid >> 5, l = tid & 31;
    const int mp = wid >> 1, np = wid & 1;     // 4 m-warps x 2 n-warps

    // ---- load A fragments into registers (once per CTA; scattered LDG, L2-served) ----
    const float* Wg = e ? Wp : Wl;
    const float* bg = e ? bp : bl;
    uint4 afrag[NCH];
    {
        const int mbase = mh * 64 + mp * 16 + (l >> 2);
#pragma unroll
        for (int q = 0; q < NCH; ++q) {
            uint32_t r[4];
#pragma unroll
            for (int reg = 0; reg < 4; ++reg) {
                int m_loc = mbase + ((reg & 1) << 3);
                int k0 = q * 16 + (l & 3) * 2 + ((reg >> 1) << 3);
                int c = k0 % CPC, k3 = k0 / CPC;     // k0 even, CPC even -> pair same k3
                const float* wr = Wg + (size_t)m_loc * KD;
                __half2 h = __floats2half2_rn(__ldg(wr + c * 3 + k3),
                                              __ldg(wr + (c + 1) * 3 + k3));
                r[reg] = *(uint32_t*)&h;
            }
            afrag[q] = make_uint4(r[0], r[1], r[2], r[3]);
        }
    }
    if (tid < 64) s_bias[tid] = bg[mh * 64 + tid];

    // ---- per-lane ldmatrix base address (matrix i/8, row i%8) ----
    //   mat 0: n rows np*16+0..7,  k bytes q*32+0
    //   mat 1: same rows,          k bytes q*32+16
    //   mat 2: n rows np*16+8..15, q*32+0
    //   mat 3: same,               q*32+16
    const uint32_t lm_base = g_u32
        + (uint32_t)((np * 16 + ((l >> 4) << 3) + (l & 7)) * KDPH * 2)
        + (uint32_t)(((l >> 3) & 1) * 16);

    // ---- gather issue: raw cp.async of pre-rounded fp16 rows ----
    auto issue_gather = [&](int t, int buf) {
        int b = t >> 7;                       // / TPB
        int tl = t & 127;
        const int* chb = children + (size_t)b * 3 * TNODE + 3 * tl * NT;
        const __half* sb = SECOND ? g_h[e] + (size_t)b * NNODE * HID
                                  : g_featsT[e] + (size_t)b * NNODE * CIN;
        uint32_t gd = g_u32 + (uint32_t)buf * GBYTES;
#pragma unroll
        for (int idx = tid; idx < 3 * NT * UNITS; idx += 256) {
            int row = idx / UNITS;
            int u   = idx & (UNITS - 1);
            int i = row / 3, k3 = row - i * 3;
            int child = __ldg(chb + row);
            cp_async16(gd + (uint32_t)(i * KDPH * 2 + k3 * CPC * 2 + u * 16),
                       sb + (size_t)child * CPC + u * 8);
        }
        cp_commit();
    };

    issue_gather(t0, 0);
    if (t0 + 1 < t1) issue_gather(t0 + 1, 1);

    for (int t = t0; t < t1; ++t) {
        int buf = (t - t0) & 1;
        if (t + 1 < t1) cp_wait<1>(); else cp_wait<0>();
        __syncthreads();

        // ---- MMA: warp tile M=16 x N=16, K=KD; A regs, B via ldmatrix.x4 ----
        float d[2][4];
#pragma unroll
        for (int nt = 0; nt < 2; ++nt)
#pragma unroll
            for (int r = 0; r < 4; ++r) d[nt][r] = 0.f;

        const uint32_t lmb = lm_base + (uint32_t)buf * GBYTES;
#pragma unroll
        for (int q = 0; q < NCH; ++q) {
            uint32_t b00, b01, b10, b11;
            ldsm_x4(b00, b01, b10, b11, lmb + q * 32);
            mma_f16(d[0], afrag[q], b00, b01);
            mma_f16(d[1], afrag[q], b10, b11);
        }

        // ---- epilogue ----
        int b = t >> 7, tl = t & 127;
        int n0 = 1 + tl * NT;
        float bb[2];
#pragma unroll
        for (int h = 0; h < 2; ++h)
            bb[h] = s_bias[mp * 16 + (l >> 2) + h * 8];

        float ls = 0.f, lss = 0.f;
        if (SECOND) {
            float mx[2] = {-3.4e38f, -3.4e38f};
#pragma unroll
            for (int nt = 0; nt < 2; ++nt)
#pragma unroll
                for (int r = 0; r < 4; ++r) {
                    float v = d[nt][r] + bb[r >> 1];
                    ls += v; lss += v * v;
                    mx[r >> 1] = fmaxf(mx[r >> 1], v);
                }
#pragma unroll
            for (int h = 0; h < 2; ++h) {
                float m = mx[h];
                m = fmaxf(m, __shfl_xor_sync(0xffffffffu, m, 1));
                m = fmaxf(m, __shfl_xor_sync(0xffffffffu, m, 2));
                if ((l & 3) == 0) {
                    int mg = mh * 64 + mp * 16 + (l >> 2) + h * 8;
                    atomicMax(&g_max2[e][b][mg], f2ord(m));
                }
            }
#pragma unroll
            for (int off = 16; off; off >>= 1) {
                ls  += __shfl_xor_sync(0xffffffffu, ls, off);
                lss += __shfl_xor_sync(0xffffffffu, lss, off);
            }
            if (l == 0) {
                atomicAdd(&g_stats2[e][b][0], ls);
                atomicAdd(&g_stats2[e][b][1], lss);
            }
            __syncthreads();                  // all warps done reading this buffer
            if (t + 2 < t1) issue_gather(t + 2, buf);
        } else {
            // stage fp16 tile [n][m] into padded smem, then coalesced STG.128
#pragma unroll
            for (int nt = 0; nt < 2; ++nt)
#pragma unroll
                for (int r = 0; r < 4; ++r) {
                    float v = d[nt][r] + bb[r >> 1];
                    int n_loc = np * 16 + nt * 8 + (l & 3) * 2 + (r & 1);
                    int m_loc = mp * 16 + (l >> 2) + (r >> 1) * 8;
                    s_stage[n_loc * SROW + m_loc] = __float2half_rn(v);
                    ls += v; lss += v * v;
                }
#pragma unroll
            for (int off = 16; off; off >>= 1) {
                ls  += __shfl_xor_sync(0xffffffffu, ls, off);
                lss += __shfl_xor_sync(0xffffffffu, lss, off);
            }
            if (l == 0) {
                atomicAdd(&g_stats1[e][b][0], ls);
                atomicAdd(&g_stats1[e][b][1], lss);
            }
            __syncthreads();                  // stage complete + all warps done reading buffer
            {
                int n = tid >> 3, u = tid & 7;
                uint4 v = *(const uint4*)(s_stage + n * SROW + u * 8);
                __half* orow = g_out1[e] + ((size_t)b * NNODE + n0 + n) * HID + mh * 64 + u * 8;
                *(uint4*)orow = v;
            }
            if (t + 2 < t1) issue_gather(t + 2, buf);
            // loop-top __syncthreads fences stage reuse (next STS happens after it)
        }
    }
}

// ---------------- finalize: LN2+relu on max, concat, mu/logvar GEMVs ---------------
__global__ void finalize_kernel(const float* __restrict__ Wmu, const float* __restrict__ bmu,
                                const float* __restrict__ Wlv, const float* __restrict__ blv,
                                float* __restrict__ out)
{
    __shared__ float comb[2 * HID];
    int b = blockIdx.x, tid = threadIdx.x;
    const float cntv = (float)(HID * NNODE);
#pragma unroll
    for (int e = 0; e < 2; ++e) {
        float st  = g_stats2[e][b][0];
        float sst = g_stats2[e][b][1];
        float mean = st / cntv;
        float var  = (sst - st * st / cntv) / (cntv - 1.f);
        float inv  = 1.f / (sqrtf(var) + EPSV);
        if (tid < HID) {
            float m = ord2f(g_max2[e][b][tid]);
            comb[e * HID + tid] = fmaxf(0.f, (m - mean) * inv);
        }
    }
    __syncthreads();
    if (tid < 64) {
        float acc = bmu[tid];
        for (int j = 0; j < 2 * HID; ++j) acc += Wmu[tid * 2 * HID + j] * comb[j];
        out[b * LAT + tid] = acc;
    } else if (tid < 128) {
        int t = tid - 64;
        float acc = blv[t];
        for (int j = 0; j < 2 * HID; ++j) acc += Wlv[t * 2 * HID + j] * comb[j];
        out[BATCH * LAT + b * LAT + t] = acc;
    }
}

// -------------------------------- launch --------------------------------
extern "C" void kernel_launch(void* const* d_in, const int* in_sizes, int n_in,
                              void* d_out, int out_size)
{
    const float* lf  = (const float*)d_in[0];
    const float* pf  = (const float*)d_in[1];
    const int*   ch  = (const int*)d_in[2];
    const float* Wl1 = (const float*)d_in[3];  const float* bl1 = (const float*)d_in[4];
    const float* Wl2 = (const float*)d_in[5];  const float* bl2 = (const float*)d_in[6];
    const float* Wp1 = (const float*)d_in[7];  const float* bp1 = (const float*)d_in[8];
    const float* Wp2 = (const float*)d_in[9];  const float* bp2 = (const float*)d_in[10];
    const float* Wmu = (const float*)d_in[11]; const float* bmu = (const float*)d_in[12];
    const float* Wlv = (const float*)d_in[13]; const float* blv = (const float*)d_in[14];
    float* out = (float*)d_out;

    // dynamic smem: stage(32*72 halves) + 2 G buffers (NT*(KD+8) halves) + bias(64 f32)
    const int SMEM1 = 32 * 72 * 2 + 2 * 32 * (192 + 8) * 2 + 256;   // 30,464 B
    const int SMEM2 = 32 * 72 * 2 + 2 * 32 * (384 + 8) * 2 + 256;   // 55,040 B
    cudaFuncSetAttribute(conv_mma_kernel<192, false>,
                         cudaFuncAttributeMaxDynamicSharedMemorySize, SMEM1);
    cudaFuncSetAttribute(conv_mma_kernel<384, true>,
                         cudaFuncAttributeMaxDynamicSharedMemorySize, SMEM2);

    init_kernel<<<(2 * BATCH * HID + 255) / 256, 256>>>();
    transpose_kernel<<<dim3((NNODE + 31) / 32, CIN / 32, 2 * BATCH), dim3(32, 8)>>>(lf, pf);
    conv_mma_kernel<192, false><<<dim3(148, 2, 2), 256, SMEM1>>>(ch, Wl1, bl1, Wp1, bp1);
    transform_kernel<<<dim3((NNODE * HID / 8 + 255) / 256, 2 * BATCH), 256>>>();
    conv_mma_kernel<384, true ><<<dim3(148, 2, 2), 256, SMEM2>>>(ch, Wl2, bl2, Wp2, bp2);
    finalize_kernel<<<BATCH, 128>>>(Wmu, bmu, Wlv, blv, out);
}